// round 7
// baseline (speedup 1.0000x reference)
#include <cuda_runtime.h>
#include <cstdint>

#define N_IMG 256
#define CHUNK_BYTES 16384u               // 8 image rows per chunk
#define CHUNKS_PER_IMG 64                // 1 MB image / 16 KB
#define N_CHUNKS (N_IMG * CHUNKS_PER_IMG) // 16384
#define ROW_BYTES 2048                   // 512 px * 4 B
#define STAGES 6
#define THREADS 288                      // warp 0 = producer, warps 1..8 consume
#define GRID_BLOCKS 296                  // 148 SM x 2
#define THRESH 0x3F000000u               // bits(0.5f); f>=0.5 <=> bits>=THRESH for f>=0

#define STAGE_SMEM (STAGES * CHUNK_BYTES)        // 98304
#define MBAR_OFF   STAGE_SMEM                    // full[s]=+s*16, empty[s]=+s*16+8
#define TID_OFF    (MBAR_OFF + STAGES * 16)      // tile_id[s] = +s*4
#define SMEM_TOTAL (TID_OFF + STAGES * 4 + 128)

// Per-image accumulators, neutral element 0 (mins stored as ~min).
__device__ int g_xmax[N_IMG];
__device__ int g_ymax[N_IMG];
__device__ unsigned g_nmax[N_IMG];
__device__ unsigned g_chunk_ctr = 0;
__device__ unsigned g_done_ctr = 0;

__device__ __forceinline__ uint32_t s2u(const void* p) {
    uint32_t a;
    asm("{ .reg .u64 t; cvta.to.shared.u64 t, %1; cvt.u32.u64 %0, t; }" : "=r"(a) : "l"(p));
    return a;
}
__device__ __forceinline__ void mbar_init(uint32_t m, uint32_t cnt) {
    asm volatile("mbarrier.init.shared.b64 [%0], %1;" :: "r"(m), "r"(cnt) : "memory");
}
__device__ __forceinline__ void mbar_arrive(uint32_t m) {
    asm volatile("mbarrier.arrive.shared.b64 _, [%0];" :: "r"(m) : "memory");
}
__device__ __forceinline__ void mbar_expect_tx(uint32_t m, uint32_t bytes) {
    asm volatile("mbarrier.arrive.expect_tx.shared.b64 _, [%0], %1;" :: "r"(m), "r"(bytes) : "memory");
}
__device__ __forceinline__ void mbar_wait(uint32_t m, uint32_t parity) {
    uint32_t done;
    asm volatile(
        "{ .reg .pred p;\n"
        " mbarrier.try_wait.parity.acquire.cta.shared::cta.b64 p, [%1], %2;\n"
        " selp.b32 %0, 1, 0, p; }"
        : "=r"(done) : "r"(m), "r"(parity) : "memory");
    if (!done) {
        asm volatile(
            "{ .reg .pred P;\n"
            "W%=:\n"
            " mbarrier.try_wait.parity.acquire.cta.shared::cta.b64 P, [%0], %1, 0x989680;\n"
            " @P bra.uni D%=;\n"
            " bra.uni W%=;\n"
            "D%=: }"
            :: "r"(m), "r"(parity) : "memory");
    }
}
__device__ __forceinline__ void bulk_copy(uint32_t smem_dst, const void* gsrc,
                                          uint32_t bytes, uint32_t mbar) {
    asm volatile(
        "cp.async.bulk.shared::cluster.global.mbarrier::complete_tx::bytes [%0], [%1], %2, [%3];"
        :: "r"(smem_dst), "l"(gsrc), "r"(bytes), "r"(mbar) : "memory");
}

__device__ __forceinline__ uint4 umax4(uint4 a, uint4 b) {
    return make_uint4(max(a.x,b.x), max(a.y,b.y), max(a.z,b.z), max(a.w,b.w));
}
__device__ __forceinline__ uint4 umin4(uint4 a, uint4 b) {
    return make_uint4(min(a.x,b.x), min(a.y,b.y), min(a.z,b.z), min(a.w,b.w));
}

// Flush one image's per-warp partial state to global accumulators.
__device__ __forceinline__ void flush_img(int img, int lane,
                                          const uint4 cmax[4], int ylast, uint4 nacc) {
    int xmax = 0;
#pragma unroll
    for (int s = 0; s < 4; s++) {
        const uint4 c = cmax[s];
        const int base = (lane + 32 * s) << 2;
        int v = 0;
        if (c.x >= THRESH) v = base + 1;
        if (c.y >= THRESH) v = base + 2;
        if (c.z >= THRESH) v = base + 3;
        if (c.w >= THRESH) v = base + 4;
        xmax = max(xmax, v);
    }
    unsigned nmin = min(min(nacc.x, nacc.y), min(nacc.z, nacc.w));
    xmax = __reduce_max_sync(0xFFFFFFFFu, xmax);
    const int ymax = __reduce_max_sync(0xFFFFFFFFu, ylast);
    nmin = __reduce_min_sync(0xFFFFFFFFu, nmin);
    if (lane == 0)      atomicMax(&g_xmax[img], xmax);
    else if (lane == 1) atomicMax(&g_ymax[img], ymax);
    else if (lane == 2) atomicMax(&g_nmax[img], ~nmin);
}

__global__ __launch_bounds__(THREADS, 2) void bb_tma_kernel(
    const float* __restrict__ mask, float* __restrict__ out) {
    extern __shared__ char smem[];
    const uint32_t sb  = s2u(smem);
    const int tid  = threadIdx.x;
    const int wid  = tid >> 5;
    const int lane = tid & 31;

    if (tid == 0) {
#pragma unroll
        for (int s = 0; s < STAGES; s++) {
            mbar_init(sb + MBAR_OFF + s * 16, 1);      // full: producer arrive + tx
            mbar_init(sb + MBAR_OFF + s * 16 + 8, 8);  // empty: 8 consumer warps
        }
    }
    __syncthreads();

    if (wid == 0) {
        // -------- Producer (lane 0 of warp 0) --------
        if (lane == 0) {
            int s = 0, eph = 1;  // producer phase trick: first empty-wait passes
            const char* gbase = reinterpret_cast<const char*>(mask);
            for (;;) {
                const unsigned c = atomicAdd(&g_chunk_ctr, 1u);
                const uint32_t full_b  = sb + MBAR_OFF + s * 16;
                const uint32_t empty_b = full_b + 8;
                mbar_wait(empty_b, eph);
                if (c < N_CHUNKS) {
                    *reinterpret_cast<unsigned*>(smem + TID_OFF + s * 4) = c;
                    mbar_expect_tx(full_b, CHUNK_BYTES);
                    bulk_copy(sb + s * CHUNK_BYTES, gbase + (size_t)c * CHUNK_BYTES,
                              CHUNK_BYTES, full_b);
                } else {
                    *reinterpret_cast<unsigned*>(smem + TID_OFF + s * 4) = 0xFFFFFFFFu;
                    mbar_arrive(full_b);   // tx=0 this phase -> flips on arrive
                    break;
                }
                if (++s == STAGES) { s = 0; eph ^= 1; }
            }
        }
    } else {
        // -------- Consumers: warp w handles row (wid-1) of each 8-row chunk --------
        const int w = wid - 1;
        int s = 0, ph = 0;
        uint4 cmax[4] = {make_uint4(0,0,0,0), make_uint4(0,0,0,0),
                         make_uint4(0,0,0,0), make_uint4(0,0,0,0)};
        uint4 nacc = make_uint4(~0u, ~0u, ~0u, ~0u);
        int ylast = 0, cur_img = -1;

        for (;;) {
            const uint32_t full_b  = sb + MBAR_OFF + s * 16;
            const uint32_t empty_b = full_b + 8;
            mbar_wait(full_b, ph);
            const unsigned c = *reinterpret_cast<const unsigned*>(smem + TID_OFF + s * 4);
            if (c == 0xFFFFFFFFu) break;

            const int img = (int)(c >> 6);             // 64 chunks per image
            if (img != cur_img) {
                if (cur_img >= 0) flush_img(cur_img, lane, cmax, ylast, nacc);
                cmax[0] = cmax[1] = cmax[2] = cmax[3] = make_uint4(0,0,0,0);
                nacc = make_uint4(~0u, ~0u, ~0u, ~0u);
                ylast = 0;
                cur_img = img;
            }
            const int row = (int)((c & 63u) << 3) + w;  // image row this warp covers

            const uint4* srow = reinterpret_cast<const uint4*>(
                smem + s * CHUNK_BYTES + w * ROW_BYTES);
            const uint4 a = srow[lane];
            const uint4 b = srow[lane + 32];
            const uint4 cc = srow[lane + 64];
            const uint4 d = srow[lane + 96];

            cmax[0] = umax4(cmax[0], a);
            cmax[1] = umax4(cmax[1], b);
            cmax[2] = umax4(cmax[2], cc);
            cmax[3] = umax4(cmax[3], d);
            nacc = umin4(nacc, umin4(umin4(a, b), umin4(cc, d)));

            const uint4 mx = umax4(umax4(a, b), umax4(cc, d));
            const unsigned m = max(max(mx.x, mx.y), max(mx.z, mx.w));
            ylast = (m >= THRESH) ? row + 1 : ylast;   // rows ascend per warp

            __syncwarp();
            if (lane == 0) mbar_arrive(empty_b);
            if (++s == STAGES) { s = 0; ph ^= 1; }
        }
        if (cur_img >= 0) flush_img(cur_img, lane, cmax, ylast, nacc);
    }

    // -------- Done ticket; last block writes outputs --------
    __shared__ bool s_last;
    __syncthreads();
    if (tid == 0) {
        __threadfence();
        s_last = (atomicAdd(&g_done_ctr, 1u) == GRID_BLOCKS - 1);
    }
    __syncthreads();
    if (!s_last) return;

    if (tid < N_IMG) {
        const int i = tid;
        const int xmax = g_xmax[i];
        const int ymax = g_ymax[i];
        const unsigned nmin = ~g_nmax[i];
        const int mnv = (nmin >= THRESH) ? 1 : 0;

        const float xminf = (float)mnv, yminf = (float)mnv;
        const float xmaxf = (float)xmax, ymaxf = (float)ymax;

        // [0,256) object_found | [256,1280) bbox_scaled | [1280,2304) bbox*2
        out[i] = ((ymaxf > yminf) && (xmaxf > xminf)) ? 1.0f : 0.0f;
        float* bb = out + 256 + i * 4;
        bb[0] = xminf; bb[1] = yminf; bb[2] = xmaxf; bb[3] = ymaxf;
        float* bb2 = out + 1280 + i * 4;
        bb2[0] = xminf * 2.0f; bb2[1] = yminf * 2.0f;
        bb2[2] = xmaxf * 2.0f; bb2[3] = ymaxf * 2.0f;

        g_xmax[i] = 0; g_ymax[i] = 0; g_nmax[i] = 0u;
        if (tid == 0) { g_chunk_ctr = 0u; g_done_ctr = 0u; }
    }
}

extern "C" void kernel_launch(void* const* d_in, const int* in_sizes, int n_in,
                              void* d_out, int out_size) {
    const float* mask = (const float*)d_in[0];
    float* out = (float*)d_out;
    static bool attr_set = false;
    if (!attr_set) {
        cudaFuncSetAttribute(bb_tma_kernel,
                             cudaFuncAttributeMaxDynamicSharedMemorySize, SMEM_TOTAL);
        attr_set = true;
    }
    bb_tma_kernel<<<GRID_BLOCKS, THREADS, SMEM_TOTAL>>>(mask, out);
}

// round 8
// speedup vs baseline: 2.0417x; 2.0417x over previous
#include <cuda_runtime.h>
#include <cstdint>

#define N_IMG 256
#define CHUNK_BYTES 32768u                 // 16 image rows
#define ROWS_PER_CHUNK 16
#define CHUNKS_PER_IMG 32
#define N_CHUNKS 8192                      // 256 MB / 32 KB
#define ROW_BYTES 2048                     // 512 px * 4 B
#define STAGES 6
#define CONS_WARPS 16
#define THREADS 544                        // warps 0..15 consume, warp 16 produces
#define GRID_BLOCKS 148                    // one block per SM
#define THRESH 0x3F000000u                 // bits(0.5f); f>=0.5 <=> bits>=THRESH (f>=0)

#define STAGE_SMEM (STAGES * CHUNK_BYTES)  // 196608
#define MBAR_OFF   STAGE_SMEM              // full[s]=+s*16, empty[s]=+s*16+8
#define SMEM_TOTAL (MBAR_OFF + STAGES * 16 + 16)

// Per-image accumulators, neutral element 0 (global min stored as ~min).
__device__ int g_xmax[N_IMG];
__device__ int g_ymax[N_IMG];
__device__ unsigned g_nmax[N_IMG];
__device__ unsigned g_done_ctr = 0;

__device__ __forceinline__ uint32_t s2u(const void* p) {
    uint32_t a;
    asm("{ .reg .u64 t; cvta.to.shared.u64 t, %1; cvt.u32.u64 %0, t; }" : "=r"(a) : "l"(p));
    return a;
}
__device__ __forceinline__ void mbar_init(uint32_t m, uint32_t cnt) {
    asm volatile("mbarrier.init.shared.b64 [%0], %1;" :: "r"(m), "r"(cnt) : "memory");
}
__device__ __forceinline__ void mbar_arrive(uint32_t m) {
    asm volatile("mbarrier.arrive.shared.b64 _, [%0];" :: "r"(m) : "memory");
}
__device__ __forceinline__ void mbar_expect_tx(uint32_t m, uint32_t bytes) {
    asm volatile("mbarrier.arrive.expect_tx.shared.b64 _, [%0], %1;" :: "r"(m), "r"(bytes) : "memory");
}
__device__ __forceinline__ void mbar_wait(uint32_t m, uint32_t parity) {
    uint32_t done;
    asm volatile(
        "{ .reg .pred p;\n"
        " mbarrier.try_wait.parity.acquire.cta.shared::cta.b64 p, [%1], %2;\n"
        " selp.b32 %0, 1, 0, p; }"
        : "=r"(done) : "r"(m), "r"(parity) : "memory");
    if (!done) {
        asm volatile(
            "{ .reg .pred P;\n"
            "W%=:\n"
            " mbarrier.try_wait.parity.acquire.cta.shared::cta.b64 P, [%0], %1, 0x989680;\n"
            " @P bra.uni D%=;\n"
            " bra.uni W%=;\n"
            "D%=: }"
            :: "r"(m), "r"(parity) : "memory");
    }
}
__device__ __forceinline__ void bulk_copy(uint32_t smem_dst, const void* gsrc,
                                          uint32_t bytes, uint32_t mbar) {
    asm volatile(
        "cp.async.bulk.shared::cluster.global.mbarrier::complete_tx::bytes [%0], [%1], %2, [%3];"
        :: "r"(smem_dst), "l"(gsrc), "r"(bytes), "r"(mbar) : "memory");
}

__device__ __forceinline__ uint4 umax4(uint4 a, uint4 b) {
    return make_uint4(max(a.x,b.x), max(a.y,b.y), max(a.z,b.z), max(a.w,b.w));
}
__device__ __forceinline__ uint4 umin4(uint4 a, uint4 b) {
    return make_uint4(min(a.x,b.x), min(a.y,b.y), min(a.z,b.z), min(a.w,b.w));
}

// Flush one image's per-warp partial state to global accumulators.
__device__ __forceinline__ void flush_img(int img, int lane,
                                          const uint4 cmax[4], int ylast, uint4 nacc) {
    int xmax = 0;
#pragma unroll
    for (int s = 0; s < 4; s++) {
        const uint4 c = cmax[s];
        const int base = (lane + 32 * s) << 2;
        int v = 0;
        if (c.x >= THRESH) v = base + 1;
        if (c.y >= THRESH) v = base + 2;
        if (c.z >= THRESH) v = base + 3;
        if (c.w >= THRESH) v = base + 4;
        xmax = max(xmax, v);
    }
    unsigned nmin = min(min(nacc.x, nacc.y), min(nacc.z, nacc.w));
    xmax = __reduce_max_sync(0xFFFFFFFFu, xmax);
    const int ymax = __reduce_max_sync(0xFFFFFFFFu, ylast);
    nmin = __reduce_min_sync(0xFFFFFFFFu, nmin);
    if (lane == 0)      atomicMax(&g_xmax[img], xmax);
    else if (lane == 1) atomicMax(&g_ymax[img], ymax);
    else if (lane == 2) atomicMax(&g_nmax[img], ~nmin);
}

__global__ __launch_bounds__(THREADS, 1) void bb_tma_kernel(
    const float* __restrict__ mask, float* __restrict__ out) {
    extern __shared__ char smem[];
    const uint32_t sb  = s2u(smem);
    const int tid  = threadIdx.x;
    const int wid  = tid >> 5;
    const int lane = tid & 31;

    if (tid == 0) {
#pragma unroll
        for (int s = 0; s < STAGES; s++) {
            mbar_init(sb + MBAR_OFF + s * 16, 1);           // full: tx-based
            mbar_init(sb + MBAR_OFF + s * 16 + 8, CONS_WARPS); // empty: 16 warps
        }
    }
    __syncthreads();

    // Static chunk range for this block; producer and consumers iterate the
    // SAME sequence, so stage<->chunk mapping needs no communication.
    const unsigned c0 = (unsigned)(((unsigned long long)blockIdx.x       * N_CHUNKS) / GRID_BLOCKS);
    const unsigned c1 = (unsigned)(((unsigned long long)(blockIdx.x + 1) * N_CHUNKS) / GRID_BLOCKS);

    if (wid == CONS_WARPS) {
        // -------- Producer: single thread issues 32 KB bulk copies --------
        if (lane == 0) {
            const char* gbase = reinterpret_cast<const char*>(mask);
            int s = 0, eph = 1;   // first empty-wait on each stage passes
            for (unsigned c = c0; c < c1; ++c) {
                const uint32_t full_b  = sb + MBAR_OFF + s * 16;
                const uint32_t empty_b = full_b + 8;
                mbar_wait(empty_b, eph);
                mbar_expect_tx(full_b, CHUNK_BYTES);
                bulk_copy(sb + s * CHUNK_BYTES, gbase + (size_t)c * CHUNK_BYTES,
                          CHUNK_BYTES, full_b);
                if (++s == STAGES) { s = 0; eph ^= 1; }
            }
        }
    } else {
        // -------- Consumers: warp w processes row w of each 16-row chunk --------
        const int w = wid;
        int s = 0, ph = 0;
        uint4 cmax[4] = {make_uint4(0,0,0,0), make_uint4(0,0,0,0),
                         make_uint4(0,0,0,0), make_uint4(0,0,0,0)};
        uint4 nacc = make_uint4(~0u, ~0u, ~0u, ~0u);
        int ylast = 0, cur_img = -1;

        for (unsigned c = c0; c < c1; ++c) {
            const uint32_t full_b  = sb + MBAR_OFF + s * 16;
            const uint32_t empty_b = full_b + 8;
            mbar_wait(full_b, ph);

            const int img = (int)(c >> 5);                  // 32 chunks per image
            if (img != cur_img) {
                if (cur_img >= 0) flush_img(cur_img, lane, cmax, ylast, nacc);
                cmax[0] = cmax[1] = cmax[2] = cmax[3] = make_uint4(0,0,0,0);
                nacc = make_uint4(~0u, ~0u, ~0u, ~0u);
                ylast = 0;
                cur_img = img;
            }
            const int row = (int)((c & 31u) << 4) + w;      // image row for this warp

            const uint4* srow = reinterpret_cast<const uint4*>(
                smem + s * CHUNK_BYTES + w * ROW_BYTES);
            const uint4 a  = srow[lane];
            const uint4 b  = srow[lane + 32];
            const uint4 cc = srow[lane + 64];
            const uint4 d  = srow[lane + 96];

            cmax[0] = umax4(cmax[0], a);
            cmax[1] = umax4(cmax[1], b);
            cmax[2] = umax4(cmax[2], cc);
            cmax[3] = umax4(cmax[3], d);
            nacc = umin4(nacc, umin4(umin4(a, b), umin4(cc, d)));

            const uint4 mx = umax4(umax4(a, b), umax4(cc, d));
            const unsigned m = max(max(mx.x, mx.y), max(mx.z, mx.w));
            ylast = (m >= THRESH) ? row + 1 : ylast;        // rows ascend per warp

            if (lane == 0) mbar_arrive(empty_b);
            if (++s == STAGES) { s = 0; ph ^= 1; }
        }
        if (cur_img >= 0) flush_img(cur_img, lane, cmax, ylast, nacc);
    }

    // -------- Done ticket; last block writes outputs --------
    __shared__ bool s_last;
    __syncthreads();
    if (tid == 0) {
        __threadfence();
        s_last = (atomicAdd(&g_done_ctr, 1u) == GRID_BLOCKS - 1);
    }
    __syncthreads();
    if (!s_last) return;

    if (tid < N_IMG) {
        const int i = tid;
        const int xmax = g_xmax[i];
        const int ymax = g_ymax[i];
        const unsigned nmin = ~g_nmax[i];
        const int mnv = (nmin >= THRESH) ? 1 : 0;   // all pixels set => mins are 1

        const float xminf = (float)mnv, yminf = (float)mnv;
        const float xmaxf = (float)xmax, ymaxf = (float)ymax;

        // [0,256) object_found | [256,1280) bbox_scaled | [1280,2304) bbox*2
        out[i] = ((ymaxf > yminf) && (xmaxf > xminf)) ? 1.0f : 0.0f;
        float* bb = out + 256 + i * 4;
        bb[0] = xminf; bb[1] = yminf; bb[2] = xmaxf; bb[3] = ymaxf;
        float* bb2 = out + 1280 + i * 4;
        bb2[0] = xminf * 2.0f; bb2[1] = yminf * 2.0f;
        bb2[2] = xmaxf * 2.0f; bb2[3] = ymaxf * 2.0f;

        g_xmax[i] = 0; g_ymax[i] = 0; g_nmax[i] = 0u;
        if (tid == 0) g_done_ctr = 0u;
    }
}

extern "C" void kernel_launch(void* const* d_in, const int* in_sizes, int n_in,
                              void* d_out, int out_size) {
    const float* mask = (const float*)d_in[0];
    float* out = (float*)d_out;
    static bool attr_set = false;
    if (!attr_set) {
        cudaFuncSetAttribute(bb_tma_kernel,
                             cudaFuncAttributeMaxDynamicSharedMemorySize, SMEM_TOTAL);
        attr_set = true;
    }
    bb_tma_kernel<<<GRID_BLOCKS, THREADS, SMEM_TOTAL>>>(mask, out);
}

// round 9
// speedup vs baseline: 2.1075x; 1.0323x over previous
#include <cuda_runtime.h>
#include <cstdint>

#define N_IMG 256
#define CHUNK_BYTES 32768u                 // 16 image rows
#define CHUNKS_PER_IMG 32
#define N_CHUNKS 8192                      // 256 MB / 32 KB
#define ROW_BYTES 2048                     // 512 px * 4 B
#define STAGES 3
#define CONS_WARPS 8                       // each handles 2 rows per chunk
#define THREADS 288                        // warps 0..7 consume, warp 8 produces
#define GRID_BLOCKS 296                    // 2 blocks per SM
#define THRESH 0x3F000000u                 // bits(0.5f); f>=0.5 <=> bits>=THRESH (f>=0)

#define STAGE_SMEM (STAGES * CHUNK_BYTES)  // 98304
#define MBAR_OFF   STAGE_SMEM              // full[s]=+s*16, empty[s]=+s*16+8
#define SMEM_TOTAL (MBAR_OFF + STAGES * 16 + 16)

// Per-image accumulators, neutral element 0 (global min stored as ~min).
__device__ int g_xmax[N_IMG];
__device__ int g_ymax[N_IMG];
__device__ unsigned g_nmax[N_IMG];
__device__ unsigned g_done_ctr = 0;

__device__ __forceinline__ uint32_t s2u(const void* p) {
    uint32_t a;
    asm("{ .reg .u64 t; cvta.to.shared.u64 t, %1; cvt.u32.u64 %0, t; }" : "=r"(a) : "l"(p));
    return a;
}
__device__ __forceinline__ void mbar_init(uint32_t m, uint32_t cnt) {
    asm volatile("mbarrier.init.shared.b64 [%0], %1;" :: "r"(m), "r"(cnt) : "memory");
}
__device__ __forceinline__ void mbar_arrive(uint32_t m) {
    asm volatile("mbarrier.arrive.shared.b64 _, [%0];" :: "r"(m) : "memory");
}
__device__ __forceinline__ void mbar_expect_tx(uint32_t m, uint32_t bytes) {
    asm volatile("mbarrier.arrive.expect_tx.shared.b64 _, [%0], %1;" :: "r"(m), "r"(bytes) : "memory");
}
__device__ __forceinline__ void mbar_wait(uint32_t m, uint32_t parity) {
    uint32_t done;
    asm volatile(
        "{ .reg .pred p;\n"
        " mbarrier.try_wait.parity.acquire.cta.shared::cta.b64 p, [%1], %2;\n"
        " selp.b32 %0, 1, 0, p; }"
        : "=r"(done) : "r"(m), "r"(parity) : "memory");
    if (!done) {
        asm volatile(
            "{ .reg .pred P;\n"
            "W%=:\n"
            " mbarrier.try_wait.parity.acquire.cta.shared::cta.b64 P, [%0], %1, 0x989680;\n"
            " @P bra.uni D%=;\n"
            " bra.uni W%=;\n"
            "D%=: }"
            :: "r"(m), "r"(parity) : "memory");
    }
}
__device__ __forceinline__ void bulk_copy(uint32_t smem_dst, const void* gsrc,
                                          uint32_t bytes, uint32_t mbar) {
    asm volatile(
        "cp.async.bulk.shared::cluster.global.mbarrier::complete_tx::bytes [%0], [%1], %2, [%3];"
        :: "r"(smem_dst), "l"(gsrc), "r"(bytes), "r"(mbar) : "memory");
}

__device__ __forceinline__ uint4 umax4(uint4 a, uint4 b) {
    return make_uint4(max(a.x,b.x), max(a.y,b.y), max(a.z,b.z), max(a.w,b.w));
}
__device__ __forceinline__ uint4 umin4(uint4 a, uint4 b) {
    return make_uint4(min(a.x,b.x), min(a.y,b.y), min(a.z,b.z), min(a.w,b.w));
}

// Flush one image's per-warp partial state to global accumulators.
__device__ __forceinline__ void flush_img(int img, int lane,
                                          const uint4 cmax[4], int ylast, uint4 nacc) {
    int xmax = 0;
#pragma unroll
    for (int s = 0; s < 4; s++) {
        const uint4 c = cmax[s];
        const int base = (lane + 32 * s) << 2;
        int v = 0;
        if (c.x >= THRESH) v = base + 1;
        if (c.y >= THRESH) v = base + 2;
        if (c.z >= THRESH) v = base + 3;
        if (c.w >= THRESH) v = base + 4;
        xmax = max(xmax, v);
    }
    unsigned nmin = min(min(nacc.x, nacc.y), min(nacc.z, nacc.w));
    xmax = __reduce_max_sync(0xFFFFFFFFu, xmax);
    const int ymax = __reduce_max_sync(0xFFFFFFFFu, ylast);
    nmin = __reduce_min_sync(0xFFFFFFFFu, nmin);
    if (lane == 0)      atomicMax(&g_xmax[img], xmax);
    else if (lane == 1) atomicMax(&g_ymax[img], ymax);
    else if (lane == 2) atomicMax(&g_nmax[img], ~nmin);
}

__global__ __launch_bounds__(THREADS, 2) void bb_tma_kernel(
    const float* __restrict__ mask, float* __restrict__ out) {
    extern __shared__ char smem[];
    const uint32_t sb  = s2u(smem);
    const int tid  = threadIdx.x;
    const int wid  = tid >> 5;
    const int lane = tid & 31;

    if (tid == 0) {
#pragma unroll
        for (int s = 0; s < STAGES; s++) {
            mbar_init(sb + MBAR_OFF + s * 16, 1);              // full: tx-based
            mbar_init(sb + MBAR_OFF + s * 16 + 8, CONS_WARPS); // empty: 8 warps
        }
    }
    __syncthreads();

    // Static chunk range; producer and consumers iterate the SAME sequence,
    // so stage<->chunk mapping needs no communication.
    const unsigned c0 = (unsigned)(((unsigned long long)blockIdx.x       * N_CHUNKS) / GRID_BLOCKS);
    const unsigned c1 = (unsigned)(((unsigned long long)(blockIdx.x + 1) * N_CHUNKS) / GRID_BLOCKS);

    if (wid == CONS_WARPS) {
        // -------- Producer: single thread issues 32 KB bulk copies --------
        if (lane == 0) {
            const char* gbase = reinterpret_cast<const char*>(mask);
            int s = 0, eph = 1;   // first empty-wait on each stage passes
            for (unsigned c = c0; c < c1; ++c) {
                const uint32_t full_b  = sb + MBAR_OFF + s * 16;
                const uint32_t empty_b = full_b + 8;
                mbar_wait(empty_b, eph);
                mbar_expect_tx(full_b, CHUNK_BYTES);
                bulk_copy(sb + s * CHUNK_BYTES, gbase + (size_t)c * CHUNK_BYTES,
                          CHUNK_BYTES, full_b);
                if (++s == STAGES) { s = 0; eph ^= 1; }
            }
        }
    } else {
        // ---- Consumers: warp w processes rows w and w+8 of each 16-row chunk ----
        const int w = wid;
        int s = 0, ph = 0;
        uint4 cmax[4] = {make_uint4(0,0,0,0), make_uint4(0,0,0,0),
                         make_uint4(0,0,0,0), make_uint4(0,0,0,0)};
        uint4 nacc = make_uint4(~0u, ~0u, ~0u, ~0u);
        int ylast = 0, cur_img = -1;

        for (unsigned c = c0; c < c1; ++c) {
            const uint32_t full_b  = sb + MBAR_OFF + s * 16;
            const uint32_t empty_b = full_b + 8;
            mbar_wait(full_b, ph);

            const int img = (int)(c >> 5);                  // 32 chunks per image
            if (img != cur_img) {
                if (cur_img >= 0) flush_img(cur_img, lane, cmax, ylast, nacc);
                cmax[0] = cmax[1] = cmax[2] = cmax[3] = make_uint4(0,0,0,0);
                nacc = make_uint4(~0u, ~0u, ~0u, ~0u);
                ylast = 0;
                cur_img = img;
            }
            const int row0 = (int)((c & 31u) << 4) + w;     // rows ascend with c
            const char* stage_base = smem + s * CHUNK_BYTES;

            // row w
            {
                const uint4* sr = reinterpret_cast<const uint4*>(stage_base + w * ROW_BYTES);
                const uint4 a  = sr[lane];
                const uint4 b  = sr[lane + 32];
                const uint4 cc = sr[lane + 64];
                const uint4 d  = sr[lane + 96];
                cmax[0] = umax4(cmax[0], a);
                cmax[1] = umax4(cmax[1], b);
                cmax[2] = umax4(cmax[2], cc);
                cmax[3] = umax4(cmax[3], d);
                nacc = umin4(nacc, umin4(umin4(a, b), umin4(cc, d)));
                const uint4 mx = umax4(umax4(a, b), umax4(cc, d));
                const unsigned m = max(max(mx.x, mx.y), max(mx.z, mx.w));
                ylast = (m >= THRESH) ? row0 + 1 : ylast;
            }
            // row w+8 (larger index, so later assignment keeps the max)
            {
                const uint4* sr = reinterpret_cast<const uint4*>(stage_base + (w + 8) * ROW_BYTES);
                const uint4 a  = sr[lane];
                const uint4 b  = sr[lane + 32];
                const uint4 cc = sr[lane + 64];
                const uint4 d  = sr[lane + 96];
                cmax[0] = umax4(cmax[0], a);
                cmax[1] = umax4(cmax[1], b);
                cmax[2] = umax4(cmax[2], cc);
                cmax[3] = umax4(cmax[3], d);
                nacc = umin4(nacc, umin4(umin4(a, b), umin4(cc, d)));
                const uint4 mx = umax4(umax4(a, b), umax4(cc, d));
                const unsigned m = max(max(mx.x, mx.y), max(mx.z, mx.w));
                ylast = (m >= THRESH) ? row0 + 8 + 1 : ylast;
            }

            if (lane == 0) mbar_arrive(empty_b);
            if (++s == STAGES) { s = 0; ph ^= 1; }
        }
        if (cur_img >= 0) flush_img(cur_img, lane, cmax, ylast, nacc);
    }

    // -------- Done ticket; last block writes outputs --------
    __shared__ bool s_last;
    __syncthreads();
    if (tid == 0) {
        __threadfence();
        s_last = (atomicAdd(&g_done_ctr, 1u) == GRID_BLOCKS - 1);
    }
    __syncthreads();
    if (!s_last) return;

    if (tid < N_IMG) {
        const int i = tid;
        const int xmax = g_xmax[i];
        const int ymax = g_ymax[i];
        const unsigned nmin = ~g_nmax[i];
        const int mnv = (nmin >= THRESH) ? 1 : 0;   // all pixels set => mins are 1

        const float xminf = (float)mnv, yminf = (float)mnv;
        const float xmaxf = (float)xmax, ymaxf = (float)ymax;

        // [0,256) object_found | [256,1280) bbox_scaled | [1280,2304) bbox*2
        out[i] = ((ymaxf > yminf) && (xmaxf > xminf)) ? 1.0f : 0.0f;
        float* bb = out + 256 + i * 4;
        bb[0] = xminf; bb[1] = yminf; bb[2] = xmaxf; bb[3] = ymaxf;
        float* bb2 = out + 1280 + i * 4;
        bb2[0] = xminf * 2.0f; bb2[1] = yminf * 2.0f;
        bb2[2] = xmaxf * 2.0f; bb2[3] = ymaxf * 2.0f;

        g_xmax[i] = 0; g_ymax[i] = 0; g_nmax[i] = 0u;
        if (tid == 0) g_done_ctr = 0u;
    }
}

extern "C" void kernel_launch(void* const* d_in, const int* in_sizes, int n_in,
                              void* d_out, int out_size) {
    const float* mask = (const float*)d_in[0];
    float* out = (float*)d_out;
    static bool attr_set = false;
    if (!attr_set) {
        cudaFuncSetAttribute(bb_tma_kernel,
                             cudaFuncAttributeMaxDynamicSharedMemorySize, SMEM_TOTAL);
        attr_set = true;
    }
    bb_tma_kernel<<<GRID_BLOCKS, THREADS, SMEM_TOTAL>>>(mask, out);
}